// round 1
// baseline (speedup 1.0000x reference)
#include <cuda_runtime.h>
#include <mma.h>
#include <math.h>

using namespace nvcuda;

#define SEQ   4096
#define DIM   512
#define BATCH 2
#define QSCALE 0.044194173824159216f  // 1/sqrt(512)

// ---------------- scratch (device globals; no allocations allowed) ----------
__device__ float g_Q[BATCH * SEQ * DIM];
__device__ float g_K[BATCH * SEQ * DIM];
__device__ float g_V[BATCH * SEQ * DIM];
__device__ float g_AT[BATCH * SEQ * DIM];  // attention output, transposed [b][d][s]

// ---------------- tf32 WMMA GEMM:  C[m,n] = sum_k A[m,k] * W[n,k] + bias[n] --
// M = 8192, N = 512, K = 512.  BM=128, BN=64, BK=16, 256 threads (8 warps 4x2),
// each warp computes 32x32 via 2x2 m16n16k8 fragments.
#define TM 128
#define TN 64
#define TK 16

__global__ __launch_bounds__(256) void gemm_bias_kernel(
    const float* __restrict__ A,
    const float* __restrict__ W0, const float* __restrict__ W1, const float* __restrict__ W2,
    const float* __restrict__ b0, const float* __restrict__ b1, const float* __restrict__ b2,
    float* __restrict__ C0, float* __restrict__ C1, float* __restrict__ C2)
{
    const float* W    = (blockIdx.z == 0) ? W0 : (blockIdx.z == 1 ? W1 : W2);
    const float* bias = (blockIdx.z == 0) ? b0 : (blockIdx.z == 1 ? b1 : b2);
    float*       C    = (blockIdx.z == 0) ? C0 : (blockIdx.z == 1 ? C1 : C2);

    __shared__ float As[TM * TK];   // row-major [128][16]
    __shared__ float Bs[TN * TK];   // Bs[n][k] = W[n0+n][k0+k]  (col-major (k,n), ld=16)
    __shared__ float Cs[TM * TN];   // epilogue staging

    const int tid = threadIdx.x;
    const int m0  = blockIdx.y * TM;
    const int n0  = blockIdx.x * TN;

    const int warpId = tid >> 5;
    const int wr = warpId >> 1;   // 0..3
    const int wc = warpId & 1;    // 0..1

    wmma::fragment<wmma::accumulator, 16, 16, 8, float> c[2][2];
    #pragma unroll
    for (int i = 0; i < 2; i++)
        #pragma unroll
        for (int j = 0; j < 2; j++)
            wmma::fill_fragment(c[i][j], 0.0f);

    for (int k0 = 0; k0 < DIM; k0 += TK) {
        // Load A tile: 128 rows x 16 cols = 512 float4, 2 per thread
        #pragma unroll
        for (int t = 0; t < 2; t++) {
            int id  = tid + t * 256;
            int row = id >> 2;
            int c4  = id & 3;
            ((float4*)As)[row * 4 + c4] =
                *(const float4*)&A[(size_t)(m0 + row) * DIM + k0 + c4 * 4];
        }
        // Load B tile: 64 rows x 16 cols = 256 float4, 1 per thread
        {
            int row = tid >> 2;
            int c4  = tid & 3;
            ((float4*)Bs)[tid] =
                *(const float4*)&W[(size_t)(n0 + row) * DIM + k0 + c4 * 4];
        }
        __syncthreads();

        #pragma unroll
        for (int kk = 0; kk < TK; kk += 8) {
            wmma::fragment<wmma::matrix_a, 16, 16, 8, wmma::precision::tf32, wmma::row_major> a[2];
            wmma::fragment<wmma::matrix_b, 16, 16, 8, wmma::precision::tf32, wmma::col_major> b[2];
            #pragma unroll
            for (int i = 0; i < 2; i++) {
                wmma::load_matrix_sync(a[i], &As[(wr * 32 + i * 16) * TK + kk], TK);
                #pragma unroll
                for (int e = 0; e < a[i].num_elements; e++)
                    a[i].x[e] = wmma::__float_to_tf32(a[i].x[e]);
            }
            #pragma unroll
            for (int j = 0; j < 2; j++) {
                wmma::load_matrix_sync(b[j], &Bs[(wc * 32 + j * 16) * TK + kk], TK);
                #pragma unroll
                for (int e = 0; e < b[j].num_elements; e++)
                    b[j].x[e] = wmma::__float_to_tf32(b[j].x[e]);
            }
            #pragma unroll
            for (int i = 0; i < 2; i++)
                #pragma unroll
                for (int j = 0; j < 2; j++)
                    wmma::mma_sync(c[i][j], a[i], b[j], c[i][j]);
        }
        __syncthreads();
    }

    // Epilogue: stage to smem, add bias, vectorized store
    #pragma unroll
    for (int i = 0; i < 2; i++)
        #pragma unroll
        for (int j = 0; j < 2; j++)
            wmma::store_matrix_sync(&Cs[(wr * 32 + i * 16) * TN + wc * 32 + j * 16],
                                    c[i][j], TN, wmma::mem_row_major);
    __syncthreads();

    #pragma unroll
    for (int t = 0; t < 8; t++) {
        int id  = tid + t * 256;
        int row = id >> 4;
        int c4  = id & 15;
        float4 v  = ((float4*)Cs)[row * 16 + c4];
        float4 bb = *(const float4*)&bias[n0 + c4 * 4];
        v.x += bb.x; v.y += bb.y; v.z += bb.z; v.w += bb.w;
        *(float4*)&C[(size_t)(m0 + row) * DIM + n0 + c4 * 4] = v;
    }
}

// ---------------- sparse attention: one CTA per query row ---------------------
// Scans the mask row in chunks, compacts kept key indices, computes gathered
// dot products (warp per key), online softmax across chunks, coalesced P*V.
// Output written TRANSPOSED: AT[b][d][s], which (flat, viewed [B*S, DIM])
// is exactly the reference's transpose(1,2).reshape shuffle.
#define CHUNK 2048

__global__ __launch_bounds__(256) void attn_kernel(
    const float* __restrict__ Q, const float* __restrict__ K, const float* __restrict__ V,
    const float* __restrict__ mask, float* __restrict__ AT)
{
    __shared__ float qs[DIM];
    __shared__ int   idxs[CHUNK];
    __shared__ float ps[CHUNK];
    __shared__ int   cnt;
    __shared__ float red[8];
    __shared__ float bcast;

    const int tid = threadIdx.x;
    const int b   = blockIdx.x >> 12;
    const int q   = blockIdx.x & (SEQ - 1);

    // load pre-scaled q row into smem
    if (tid < 128) {
        float4 v = *(const float4*)&Q[((size_t)b * SEQ + q) * DIM + tid * 4];
        v.x *= QSCALE; v.y *= QSCALE; v.z *= QSCALE; v.w *= QSCALE;
        *(float4*)&qs[tid * 4] = v;
    }

    const float* mrow = mask + ((size_t)b * SEQ + q) * SEQ;
    float m = -INFINITY, l = 0.0f, acc0 = 0.0f, acc1 = 0.0f;

    for (int ch = 0; ch < SEQ / CHUNK; ++ch) {
        if (tid == 0) cnt = 0;
        __syncthreads();  // also covers qs visibility on first iter

        const int base = ch * CHUNK;
        #pragma unroll
        for (int j = tid; j < CHUNK; j += 256) {
            if (mrow[base + j] > 0.95f) {
                int p = atomicAdd(&cnt, 1);
                idxs[p] = base + j;
            }
        }
        __syncthreads();
        const int n = cnt;  // uniform

        if (n) {
            const int warp = tid >> 5, lane = tid & 31;
            // scores: one warp per kept key
            for (int i = warp; i < n; i += 8) {
                const float4* kr = (const float4*)&K[((size_t)b * SEQ + idxs[i]) * DIM];
                float s = 0.0f;
                #pragma unroll
                for (int u = 0; u < 4; u++) {
                    float4 kv = kr[lane + u * 32];
                    float4 qv = *(const float4*)&qs[(lane + u * 32) * 4];
                    s += kv.x * qv.x + kv.y * qv.y + kv.z * qv.z + kv.w * qv.w;
                }
                #pragma unroll
                for (int o = 16; o; o >>= 1) s += __shfl_xor_sync(0xffffffffu, s, o);
                if (lane == 0) ps[i] = s;
            }
            __syncthreads();

            // block max over ps[0..n)
            float cm = -INFINITY;
            for (int i = tid; i < n; i += 256) cm = fmaxf(cm, ps[i]);
            #pragma unroll
            for (int o = 16; o; o >>= 1) cm = fmaxf(cm, __shfl_xor_sync(0xffffffffu, cm, o));
            if ((tid & 31) == 0) red[tid >> 5] = cm;
            __syncthreads();
            if (tid < 32) {
                float v2 = (tid < 8) ? red[tid] : -INFINITY;
                #pragma unroll
                for (int o = 4; o; o >>= 1) v2 = fmaxf(v2, __shfl_xor_sync(0xffffffffu, v2, o));
                if (tid == 0) bcast = v2;
            }
            __syncthreads();

            const float newm = fmaxf(m, bcast);
            const float r    = __expf(m - newm);  // m==-inf -> 0
            acc0 *= r; acc1 *= r; l *= r;
            m = newm;

            // exponentiate + block sum
            float cs = 0.0f;
            for (int i = tid; i < n; i += 256) {
                float p = __expf(ps[i] - m);
                ps[i] = p;
                cs += p;
            }
            #pragma unroll
            for (int o = 16; o; o >>= 1) cs += __shfl_xor_sync(0xffffffffu, cs, o);
            if ((tid & 31) == 0) red[tid >> 5] = cs;
            __syncthreads();
            if (tid < 32) {
                float v2 = (tid < 8) ? red[tid] : 0.0f;
                #pragma unroll
                for (int o = 4; o; o >>= 1) v2 += __shfl_xor_sync(0xffffffffu, v2, o);
                if (tid == 0) bcast = v2;
            }
            __syncthreads();
            l += bcast;

            // accumulate P*V: all threads walk the same key sequence ->
            // V reads are coalesced 1KB segments across the CTA
            const float* Vb = V + (size_t)b * SEQ * DIM;
            #pragma unroll 4
            for (int i = 0; i < n; i++) {
                const float  p  = ps[i];
                const float* vr = Vb + (size_t)idxs[i] * DIM;
                acc0 += p * vr[tid];
                acc1 += p * vr[tid + 256];
            }
        }
        __syncthreads();  // protect idxs/ps/cnt reuse next chunk
    }

    const float inv = 1.0f / l;
    AT[((size_t)b * DIM + tid)       * SEQ + q] = acc0 * inv;
    AT[((size_t)b * DIM + tid + 256) * SEQ + q] = acc1 * inv;
}

// ---------------- launch ------------------------------------------------------
extern "C" void kernel_launch(void* const* d_in, const int* in_sizes, int n_in,
                              void* d_out, int out_size)
{
    const float* x    = (const float*)d_in[0];
    const float* mask = (const float*)d_in[1];
    const float* Wq   = (const float*)d_in[2];
    const float* bq   = (const float*)d_in[3];
    const float* Wk   = (const float*)d_in[4];
    const float* bk   = (const float*)d_in[5];
    const float* Wv   = (const float*)d_in[6];
    const float* bv   = (const float*)d_in[7];
    const float* Wo   = (const float*)d_in[8];
    const float* bo   = (const float*)d_in[9];

    float *Q, *K, *V, *AT;
    cudaGetSymbolAddress((void**)&Q,  g_Q);
    cudaGetSymbolAddress((void**)&K,  g_K);
    cudaGetSymbolAddress((void**)&V,  g_V);
    cudaGetSymbolAddress((void**)&AT, g_AT);

    // QKV projections (z = 0/1/2 selects weight set)
    dim3 gq(DIM / TN, (BATCH * SEQ) / TM, 3);
    gemm_bias_kernel<<<gq, 256>>>(x, Wq, Wk, Wv, bq, bk, bv, Q, K, V);

    // sparse attention, output transposed into AT
    attn_kernel<<<BATCH * SEQ, 256>>>(Q, K, V, mask, AT);

    // output projection on the (implicitly shuffled) AT buffer
    dim3 go(DIM / TN, (BATCH * SEQ) / TM, 1);
    gemm_bias_kernel<<<go, 256>>>(AT, Wo, Wo, Wo, bo, bo, bo,
                                  (float*)d_out, (float*)d_out, (float*)d_out);
}